// round 3
// baseline (speedup 1.0000x reference)
#include <cuda_runtime.h>

// out[b][e] = sum_n v[b][n][e]
// Reference's softmax is over a size-1 axis => identically 1.0; everything
// except the v-reduction is dead code. Pure HBM-streaming problem: 256 MB read.
//
// Decomposition: exactly one wave of 1184 CTAs (148 SMs x 8 resident), each CTA
// owning a contiguous 55-56 row slab of one batch b. Per-SM work is balanced to
// within one row (4 KB), eliminating the multi-wave / ragged-wave tail that
// capped previous rounds at ~76% DRAM.

#define BSZ 32
#define NQ  2048
#define EMB 1024
#define CTAS_PER_B 37
#define GRID (BSZ * CTAS_PER_B)          // 1184 = 148 * 8
#define ROWS_BASE (NQ / CTAS_PER_B)      // 55
#define ROWS_REM  (NQ - CTAS_PER_B * ROWS_BASE)  // 13

__global__ void zero_out_kernel(float* __restrict__ out, int n) {
    int i = blockIdx.x * blockDim.x + threadIdx.x;
    if (i < n) out[i] = 0.0f;
}

__global__ __launch_bounds__(256, 8) void vsum_kernel(const float* __restrict__ v,
                                                      float* __restrict__ out) {
    const int cta = blockIdx.x;            // 0..1183
    const int b   = cta & (BSZ - 1);       // 0..31
    const int j   = cta >> 5;              // 0..36  slab index within b

    const int start = j * ROWS_BASE + (j < ROWS_REM ? j : ROWS_REM);
    const int count = ROWS_BASE + (j < ROWS_REM ? 1 : 0);   // 55 or 56

    const int e4 = threadIdx.x;            // 0..255 -> float4 column

    const float4* vp = reinterpret_cast<const float4*>(v) +
                       ((size_t)b * NQ + start) * (EMB / 4) + e4;

    float4 a0 = make_float4(0.f, 0.f, 0.f, 0.f);
    float4 a1 = make_float4(0.f, 0.f, 0.f, 0.f);

    int n = 0;
    #pragma unroll 4
    for (; n + 2 <= count; n += 2) {
        float4 x0 = vp[(size_t)n       * (EMB / 4)];
        float4 x1 = vp[(size_t)(n + 1) * (EMB / 4)];
        a0.x += x0.x; a0.y += x0.y; a0.z += x0.z; a0.w += x0.w;
        a1.x += x1.x; a1.y += x1.y; a1.z += x1.z; a1.w += x1.w;
    }
    if (n < count) {
        float4 x0 = vp[(size_t)n * (EMB / 4)];
        a0.x += x0.x; a0.y += x0.y; a0.z += x0.z; a0.w += x0.w;
    }

    float* o = out + (size_t)b * EMB + (size_t)e4 * 4;
    atomicAdd(o + 0, a0.x + a1.x);
    atomicAdd(o + 1, a0.y + a1.y);
    atomicAdd(o + 2, a0.z + a1.z);
    atomicAdd(o + 3, a0.w + a1.w);
}

extern "C" void kernel_launch(void* const* d_in, const int* in_sizes, int n_in,
                              void* d_out, int out_size) {
    // metadata order: q, k, v, Wq, bq, Wk, bk, Ws, bs
    const float* v = (const float*)d_in[2];
    float* out = (float*)d_out;

    // d_out is poisoned; zero it before accumulation.
    zero_out_kernel<<<(out_size + 255) / 256, 256>>>(out, out_size);

    vsum_kernel<<<GRID, 256>>>(v, out);
}

// round 4
// speedup vs baseline: 1.0603x; 1.0603x over previous
#include <cuda_runtime.h>

// out[b][e] = sum_n v[b][n][e]
// Reference's softmax is over a size-1 axis => identically 1.0; everything
// except the v-reduction is dead code. Pure HBM-streaming: 256 MB read.
//
// Single launch, no atomics, no zero-init: grid (32 b, 32 col-chunks); each CTA
// reduces its 128-byte column stripe over all 2048 rows and writes the final
// 32 output floats with plain stores. Every output element written exactly once.

#define BSZ 32
#define NQ  2048
#define EMB 1024

__global__ __launch_bounds__(256) void vsum_kernel(const float* __restrict__ v,
                                                   float* __restrict__ out) {
    const int b   = blockIdx.x;          // 0..31
    const int c   = blockIdx.y;          // 0..31 column chunk (32 floats = 128 B)
    const int col = threadIdx.x & 7;     // float4 within chunk
    const int r   = threadIdx.x >> 3;    // 0..31 row slot

    const float4* vp = reinterpret_cast<const float4*>(
                           v + (size_t)b * NQ * EMB + (size_t)c * 32) + col;

    float4 a0 = make_float4(0.f, 0.f, 0.f, 0.f);
    float4 a1 = make_float4(0.f, 0.f, 0.f, 0.f);

    // Thread handles rows r, r+32, ..., r+2016 (64 rows). Two accumulator
    // chains; unroll 4 => 8 independent LDG.128 in flight per window.
    #pragma unroll 4
    for (int n = 0; n < 64; n += 2) {
        float4 x0 = vp[(size_t)(r + (n + 0) * 32) * (EMB / 4)];
        float4 x1 = vp[(size_t)(r + (n + 1) * 32) * (EMB / 4)];
        a0.x += x0.x; a0.y += x0.y; a0.z += x0.z; a0.w += x0.w;
        a1.x += x1.x; a1.y += x1.y; a1.z += x1.z; a1.w += x1.w;
    }

    float4 a;
    a.x = a0.x + a1.x; a.y = a0.y + a1.y;
    a.z = a0.z + a1.z; a.w = a0.w + a1.w;

    // Within a warp: 4 row-slots per col live at lane bits 3,4 -> xor-reduce.
    #pragma unroll
    for (int m = 8; m <= 16; m <<= 1) {
        a.x += __shfl_xor_sync(0xffffffff, a.x, m);
        a.y += __shfl_xor_sync(0xffffffff, a.y, m);
        a.z += __shfl_xor_sync(0xffffffff, a.z, m);
        a.w += __shfl_xor_sync(0xffffffff, a.w, m);
    }

    // Cross-warp: 8 warps x 8 cols via smem.
    __shared__ float4 red[8][8];
    const int warp = threadIdx.x >> 5;
    const int lane = threadIdx.x & 31;
    if (lane < 8) red[warp][lane] = a;
    __syncthreads();

    if (threadIdx.x < 8) {
        float4 s = red[0][threadIdx.x];
        #pragma unroll
        for (int w = 1; w < 8; w++) {
            float4 t = red[w][threadIdx.x];
            s.x += t.x; s.y += t.y; s.z += t.z; s.w += t.w;
        }
        reinterpret_cast<float4*>(out)[(size_t)b * (EMB / 4) + c * 8 + threadIdx.x] = s;
    }
}

extern "C" void kernel_launch(void* const* d_in, const int* in_sizes, int n_in,
                              void* d_out, int out_size) {
    // metadata order: q, k, v, Wq, bq, Wk, bk, Ws, bs
    const float* v = (const float*)d_in[2];
    float* out = (float*)d_out;

    dim3 grid(BSZ, 32);
    vsum_kernel<<<grid, 256>>>(v, out);
}